// round 1
// baseline (speedup 1.0000x reference)
#include <cuda_runtime.h>
#include <math.h>

#define SCALEF 0.70710678118654752440f

// ---------------- scratch (__device__ globals: no allocation allowed) ----------------
__device__ float g_vec[4*64*256];      // a^v tables  [m][v][hn]
__device__ float g_vB[2*256];          // sigmoid(B1), sigmoid(B2)
__device__ float g_c1[256];            // C1*SCALE
__device__ float g_c2[256];            // C2*SCALE
__device__ float g_outs[2*1024*256];   // per-dir segment sums [dir][l][hn]
__device__ float g_kk[128*1024];       // conv kernel [h][l=p*32+q], boundary-scaled
__device__ float g_Keff[32*63*64];     // combined 63x63 correlation kernel per channel
__device__ float g_xt[8*32*64*64];     // x transposed to (b,c,i,j)
__device__ float g_yt[8*32*64*64];     // conv output (b,c,i,j)

// ---------------- kernel A: build vec tables ----------------
__global__ void k_vec(const float* __restrict__ A1, const float* __restrict__ A2,
                      const float* __restrict__ A3, const float* __restrict__ A4,
                      const float* __restrict__ B1, const float* __restrict__ B2,
                      const float* __restrict__ C1, const float* __restrict__ C2)
{
    int t = threadIdx.x;  // hn = h*2+n, 0..255
    const float* As[4] = {A1, A2, A3, A4};
    for (int m = 0; m < 4; m++) {
        float a = 1.0f / (1.0f + expf(-As[m][t]));   // sigmoid
        float p = 1.0f;
        for (int v = 0; v < 64; v++) {
            g_vec[m*16384 + v*256 + t] = p;          // a^v
            p *= a;
        }
    }
    g_vB[t]       = 1.0f / (1.0f + expf(-B1[t]));
    g_vB[256 + t] = 1.0f / (1.0f + expf(-B2[t]));
    g_c1[t] = C1[t] * SCALEF;
    g_c2[t] = C2[t] * SCALEF;
}

// ---------------- kernel B: GEMM-product + segment reduction ----------------
// block = (l, dir). Computes outs[dir][l][hn] = sum_{j<64} prod_m (M_m[l*64+j,:] . vec_m[:,hn])
__global__ __launch_bounds__(256, 1) void k_prod(
    const float* __restrict__ M1, const float* __restrict__ M2,
    const float* __restrict__ M3, const float* __restrict__ M4,
    const float* __restrict__ MB,
    const float* __restrict__ N1, const float* __restrict__ N2,
    const float* __restrict__ N3, const float* __restrict__ N4,
    const float* __restrict__ NB)
{
    int l   = blockIdx.x;   // 0..1023
    int dir = blockIdx.y;   // 0..1
    const float* Mlist[4];
    const float* MBp;
    if (dir == 0) { Mlist[0]=M1; Mlist[1]=M2; Mlist[2]=M3; Mlist[3]=M4; MBp=MB; }
    else          { Mlist[0]=N1; Mlist[1]=N2; Mlist[2]=N3; Mlist[3]=N4; MBp=NB; }

    __shared__ float sM[64*65];     // 64 rows x 64 v, pad 65 (conflict-free)
    __shared__ float sV[16*256];    // vec chunk: 16 v x 256 hn
    __shared__ float sRed[8*256];   // cross-warp reduction

    int tid = threadIdx.x;
    int tj  = tid >> 5;     // warp id -> j group (uniform within warp: broadcast LDS)
    int tt  = tid & 31;
    int j0  = tj * 8;
    int t0  = tt * 8;

    float prod[8][8];
    float acc[8][8];

    for (int m = 0; m < 4; m++) {
        __syncthreads();   // protect sM against previous m's readers
        const float* Mg = Mlist[m] + (size_t)l * 4096;
        for (int idx = tid; idx < 4096; idx += 256) {
            int j = idx >> 6, v = idx & 63;
            sM[j*65 + v] = Mg[idx];
        }
        #pragma unroll
        for (int a = 0; a < 8; a++)
            #pragma unroll
            for (int k = 0; k < 8; k++) acc[a][k] = 0.0f;

        for (int vc = 0; vc < 4; vc++) {
            __syncthreads();
            const float* Vg = g_vec + m*16384 + vc*4096;
            for (int idx = tid; idx < 4096; idx += 256) sV[idx] = Vg[idx];
            __syncthreads();
            #pragma unroll 4
            for (int v = 0; v < 16; v++) {
                float a8[8], b8[8];
                #pragma unroll
                for (int jj = 0; jj < 8; jj++) a8[jj] = sM[(j0+jj)*65 + vc*16 + v];
                #pragma unroll
                for (int k = 0; k < 8; k++)  b8[k]  = sV[v*256 + t0 + k];
                #pragma unroll
                for (int jj = 0; jj < 8; jj++)
                    #pragma unroll
                    for (int k = 0; k < 8; k++)
                        acc[jj][k] = fmaf(a8[jj], b8[k], acc[jj][k]);
            }
        }
        if (m == 0) {
            #pragma unroll
            for (int jj = 0; jj < 8; jj++)
                #pragma unroll
                for (int k = 0; k < 8; k++) prod[jj][k] = acc[jj][k];
        } else {
            #pragma unroll
            for (int jj = 0; jj < 8; jj++)
                #pragma unroll
                for (int k = 0; k < 8; k++) prod[jj][k] *= acc[jj][k];
        }
    }

    // B-matrix term: cur_B[r,hn] = MB[r,0]*sig(B1)[hn] + MB[r,1]*sig(B2)[hn]
    {
        float mb0[8], mb1[8], vb0[8], vb1[8];
        #pragma unroll
        for (int jj = 0; jj < 8; jj++) {
            int r = l*64 + j0 + jj;
            mb0[jj] = MBp[r*2];
            mb1[jj] = MBp[r*2 + 1];
        }
        #pragma unroll
        for (int k = 0; k < 8; k++) { vb0[k] = g_vB[t0+k]; vb1[k] = g_vB[256+t0+k]; }
        #pragma unroll
        for (int jj = 0; jj < 8; jj++)
            #pragma unroll
            for (int k = 0; k < 8; k++)
                prod[jj][k] *= fmaf(mb0[jj], vb0[k], mb1[jj]*vb1[k]);
    }

    // reduce over j (8 in-thread + 8 across warps)
    float ps[8];
    #pragma unroll
    for (int k = 0; k < 8; k++) {
        float s = 0.0f;
        #pragma unroll
        for (int jj = 0; jj < 8; jj++) s += prod[jj][k];
        ps[k] = s;
    }
    #pragma unroll
    for (int k = 0; k < 8; k++) sRed[tj*256 + t0 + k] = ps[k];
    __syncthreads();
    float s = 0.0f;
    #pragma unroll
    for (int w = 0; w < 8; w++) s += sRed[w*256 + tid];
    g_outs[(dir*1024 + l)*256 + tid] = s;
}

// ---------------- kernel C1: combine dirs with C1/C2, boundary scaling ----------------
__global__ void k_comb()
{
    int idx = blockIdx.x * 256 + threadIdx.x;  // 128*1024
    int h = idx >> 10;
    int l = idx & 1023;
    const float* o0 = g_outs + l*256;
    const float* o1 = g_outs + 2*1024*256/2 + l*256;  // dir 1 base = 262144
    int t = h*2;
    float v = o0[t]*g_c1[t] + o0[t+1]*g_c1[t+1] + o1[t]*g_c2[t] + o1[t+1]*g_c2[t+1];
    int li = l >> 5, lj = l & 31;
    float f = 1.0f;
    if (li == 0) f *= 2.0f;
    if (lj == 0) f *= 2.0f;
    if (li == 0 && lj == 0) f *= 0.25f;   // 2*2/4 = 1 at corner
    g_kk[h*1024 + l] = v * f;
}

// ---------------- kernel C2: fold 4 flip-directions into one 63x63 kernel ----------------
// y[i,j] = sum_{dp,dq in [-31,31]} Keff[c][dp][dq] * x[i+dp][j+dq]
__global__ void k_keff()
{
    int dqi = threadIdx.x;
    if (dqi >= 63) return;
    int dpi = blockIdx.x;   // 0..62
    int c   = blockIdx.y;   // 0..31
    int dp = dpi - 31, dq = dqi - 31;
    float v = 0.0f;
    if (dp <= 0 && dq <= 0) v += g_kk[(c      )*1024 + (-dp)*32 + (-dq)];  // x[i-p,j-q]
    if (dp >= 0 && dq <= 0) v += g_kk[(c + 32 )*1024 + ( dp)*32 + (-dq)];  // x[i+p,j-q]
    if (dp <= 0 && dq >= 0) v += g_kk[(c + 64 )*1024 + (-dp)*32 + ( dq)];  // x[i-p,j+q]
    if (dp >= 0 && dq >= 0) v += g_kk[(c + 96 )*1024 + ( dp)*32 + ( dq)];  // x[i+p,j+q]
    g_Keff[(c*63 + dpi)*64 + dqi] = v;
}

// ---------------- kernel X: transpose x (b,i,j,c) -> (b,c,i,j) ----------------
__global__ void k_xt(const float* __restrict__ x)
{
    int idx = blockIdx.x * 256 + threadIdx.x;   // 1048576
    int j = idx & 63;
    int i = (idx >> 6) & 63;
    int c = (idx >> 12) & 31;
    int b = idx >> 17;
    g_xt[idx] = x[((b*64 + i)*64 + j)*32 + c];
}

// ---------------- kernel D: direct 63x63 correlation, per (b,c) plane ----------------
__global__ __launch_bounds__(256, 2) void k_conv()
{
    int c  = blockIdx.x;        // 0..31
    int b  = blockIdx.y;        // 0..7
    int i0 = blockIdx.z * 32;   // half-plane of output rows
    __shared__ float xs[95*128];  // rows [i0-31, i0+63], cols [-31, 94], zero-padded

    int tid = threadIdx.x;
    const float* xp = g_xt + (b*32 + c)*4096;
    for (int idx = tid; idx < 95*128; idx += 256) {
        int r  = idx >> 7, cj = idx & 127;
        int gi = i0 - 31 + r, gj = cj - 31;
        float v = 0.0f;
        if ((unsigned)gi < 64u && (unsigned)gj < 64u) v = xp[gi*64 + gj];
        xs[idx] = v;
    }
    __syncthreads();

    int j  = tid & 63;
    int ig = tid >> 6;   // 0..3  -> 8-row output tile
    int ib = ig * 8;
    float acc[8];
    #pragma unroll
    for (int r = 0; r < 8; r++) acc[r] = 0.0f;

    const float* Kc = g_Keff + c*63*64;
    for (int dqi = 0; dqi < 63; dqi++) {
        int cj = j + dqi;          // smem col (already offset by +31 padding)
        float w[8];                // sliding window over rows
        #pragma unroll
        for (int k = 0; k < 8; k++) w[k] = xs[(ib + k)*128 + cj];
        #pragma unroll
        for (int dpi = 0; dpi < 63; dpi++) {
            float kv = __ldg(Kc + dpi*64 + dqi);
            #pragma unroll
            for (int r = 0; r < 8; r++)
                acc[r] = fmaf(kv, w[(dpi + r) & 7], acc[r]);
            if (dpi < 62) w[dpi & 7] = xs[(ib + dpi + 8)*128 + cj];
        }
    }

    float* yp = g_yt + (b*32 + c)*4096;
    #pragma unroll
    for (int r = 0; r < 8; r++)
        yp[(i0 + ib + r)*64 + j] = acc[r];
}

// ---------------- kernel E: out = y @ W^T + b ----------------
__global__ __launch_bounds__(256, 4) void k_out(const float* __restrict__ W,
                                                const float* __restrict__ bias,
                                                float* __restrict__ out)
{
    int ip = blockIdx.x;   // i pair 0..31
    int b  = blockIdx.y;   // 0..7
    __shared__ float ys[2*32*64];   // [ii][c][j]
    __shared__ float Wt[32*32];     // transposed: Wt[c][e]

    int tid = threadIdx.x;
    for (int idx = tid; idx < 4096; idx += 256) {
        int ii = idx >> 11;
        int c  = (idx >> 6) & 31;
        int jx = idx & 63;
        ys[idx] = g_yt[((b*32 + c)*64 + ip*2 + ii)*64 + jx];
    }
    for (int idx = tid; idx < 1024; idx += 256) {
        int e = idx & 31, cc = idx >> 5;
        Wt[cc*32 + e] = W[e*32 + cc];
    }
    __syncthreads();

    int e0 = (tid & 7) * 4;
    int j0 = (tid >> 3) * 2;
    float acc[2][2][4];
    #pragma unroll
    for (int ii = 0; ii < 2; ii++)
        #pragma unroll
        for (int jj = 0; jj < 2; jj++)
            #pragma unroll
            for (int k = 0; k < 4; k++) acc[ii][jj][k] = bias[e0 + k];

    for (int cc = 0; cc < 32; cc++) {
        float yv[2][2];
        #pragma unroll
        for (int ii = 0; ii < 2; ii++)
            #pragma unroll
            for (int jj = 0; jj < 2; jj++) yv[ii][jj] = ys[ii*2048 + cc*64 + j0 + jj];
        float wv[4];
        #pragma unroll
        for (int k = 0; k < 4; k++) wv[k] = Wt[cc*32 + e0 + k];
        #pragma unroll
        for (int ii = 0; ii < 2; ii++)
            #pragma unroll
            for (int jj = 0; jj < 2; jj++)
                #pragma unroll
                for (int k = 0; k < 4; k++)
                    acc[ii][jj][k] = fmaf(yv[ii][jj], wv[k], acc[ii][jj][k]);
    }

    #pragma unroll
    for (int ii = 0; ii < 2; ii++)
        #pragma unroll
        for (int jj = 0; jj < 2; jj++) {
            float* op = out + ((size_t)((b*64 + ip*2 + ii)*64 + j0 + jj))*32 + e0;
            #pragma unroll
            for (int k = 0; k < 4; k++) op[k] = acc[ii][jj][k];
        }
}

// ---------------- launch ----------------
extern "C" void kernel_launch(void* const* d_in, const int* in_sizes, int n_in,
                              void* d_out, int out_size)
{
    const float* x    = (const float*)d_in[0];
    const float* Mh1  = (const float*)d_in[1];
    const float* Mh2  = (const float*)d_in[2];
    const float* Mh3  = (const float*)d_in[3];
    const float* Mh4  = (const float*)d_in[4];
    const float* MhB  = (const float*)d_in[5];
    const float* Mv1  = (const float*)d_in[6];
    const float* Mv2  = (const float*)d_in[7];
    const float* Mv3  = (const float*)d_in[8];
    const float* Mv4  = (const float*)d_in[9];
    const float* MvB  = (const float*)d_in[10];
    const float* A1   = (const float*)d_in[11];
    const float* A2   = (const float*)d_in[12];
    const float* A3   = (const float*)d_in[13];
    const float* A4   = (const float*)d_in[14];
    const float* B1   = (const float*)d_in[15];
    const float* B2   = (const float*)d_in[16];
    const float* C1   = (const float*)d_in[17];
    const float* C2   = (const float*)d_in[18];
    const float* W    = (const float*)d_in[19];
    const float* bias = (const float*)d_in[20];
    float* out = (float*)d_out;

    k_vec <<<1, 256>>>(A1, A2, A3, A4, B1, B2, C1, C2);
    k_prod<<<dim3(1024, 2), 256>>>(Mh1, Mh2, Mh3, Mh4, MhB, Mv1, Mv2, Mv3, Mv4, MvB);
    k_comb<<<512, 256>>>();
    k_keff<<<dim3(63, 32), 64>>>();
    k_xt  <<<4096, 256>>>(x);
    k_conv<<<dim3(32, 8, 2), 256>>>();
    k_out <<<dim3(32, 8), 256>>>(W, bias, out);
}

// round 2
// speedup vs baseline: 1.5763x; 1.5763x over previous
#include <cuda_runtime.h>
#include <math.h>

#define SCALEF 0.70710678118654752440f
typedef unsigned long long u64;

// ---------------- f32x2 helpers ----------------
__device__ __forceinline__ u64 dup_f(float x){ u64 r; asm("mov.b64 %0,{%1,%1};" : "=l"(r) : "f"(x)); return r; }
__device__ __forceinline__ u64 pack2(float lo, float hi){ u64 r; asm("mov.b64 %0,{%1,%2};" : "=l"(r) : "f"(lo), "f"(hi)); return r; }
__device__ __forceinline__ u64 fma2(u64 a, u64 b, u64 c){ u64 d; asm("fma.rn.f32x2 %0,%1,%2,%3;" : "=l"(d) : "l"(a),"l"(b),"l"(c)); return d; }
__device__ __forceinline__ u64 mul2(u64 a, u64 b){ u64 d; asm("mul.rn.f32x2 %0,%1,%2;" : "=l"(d) : "l"(a),"l"(b)); return d; }
__device__ __forceinline__ u64 add2(u64 a, u64 b){ u64 d; asm("add.rn.f32x2 %0,%1,%2;" : "=l"(d) : "l"(a),"l"(b)); return d; }
__device__ __forceinline__ float lo_f(u64 x){ float a,b; asm("mov.b64 {%0,%1},%2;" : "=f"(a),"=f"(b) : "l"(x)); return a; }
__device__ __forceinline__ float hi_f(u64 x){ float a,b; asm("mov.b64 {%0,%1},%2;" : "=f"(a),"=f"(b) : "l"(x)); return b; }

// ---------------- scratch ----------------
__device__ float g_vec[4*64*256];      // a^v tables  [m][v][hn]
__device__ float g_vB[2*256];          // sigmoid(B1), sigmoid(B2)
__device__ float g_c1[256];
__device__ float g_c2[256];
__device__ float g_outs[2*1024*256];   // [dir][l][hn]
__device__ float g_kk[128*1024];       // conv kernel [h][l], boundary-scaled
__device__ u64   g_K2[32*63*64];       // combined corr kernel, dup-packed, [c][dqi][dpi pad64]
__device__ u64   g_xt2[32*4*64*64];    // x, b-pair packed: [c][bp][i][j] = (x[2bp], x[2bp+1])
__device__ u64   g_yt2[32*4*64*64];    // conv output, same packing

// ---------------- kernel A: build vec tables ----------------
__global__ void k_vec(const float* __restrict__ A1, const float* __restrict__ A2,
                      const float* __restrict__ A3, const float* __restrict__ A4,
                      const float* __restrict__ B1, const float* __restrict__ B2,
                      const float* __restrict__ C1, const float* __restrict__ C2)
{
    int t = threadIdx.x;  // hn 0..255
    const float* As[4] = {A1, A2, A3, A4};
    for (int m = 0; m < 4; m++) {
        float a = 1.0f / (1.0f + expf(-As[m][t]));
        float p = 1.0f;
        for (int v = 0; v < 64; v++) {
            g_vec[m*16384 + v*256 + t] = p;
            p *= a;
        }
    }
    g_vB[t]       = 1.0f / (1.0f + expf(-B1[t]));
    g_vB[256 + t] = 1.0f / (1.0f + expf(-B2[t]));
    g_c1[t] = C1[t] * SCALEF;
    g_c2[t] = C2[t] * SCALEF;
}

// ---------------- kernel B: GEMM-product + segment reduction (f32x2 packed) ----------------
// block = (l, dir). outs[dir][l][hn] = sum_j prod_m (M_m[l*64+j,:] . vec_m[:,hn])
// smem (dynamic): sMd: dup-packed M rows [v][j] pitch66  (64*66 u64 = 33792B)
//                 sV2: vec pairs [v][128]                (8192 u64  = 65536B)
//                 sRed: reduction [8][128] u64           (1024 u64  =  8192B)
__global__ __launch_bounds__(256, 1) void k_prod(
    const float* __restrict__ M1, const float* __restrict__ M2,
    const float* __restrict__ M3, const float* __restrict__ M4,
    const float* __restrict__ MB,
    const float* __restrict__ N1, const float* __restrict__ N2,
    const float* __restrict__ N3, const float* __restrict__ N4,
    const float* __restrict__ NB)
{
    extern __shared__ u64 smemP[];
    u64* sMd  = smemP;              // 64*66
    u64* sV2  = smemP + 64*66;      // 64*128
    u64* sRed = sV2 + 8192;         // 8*128

    int l   = blockIdx.x;
    int dir = blockIdx.y;
    const float* Mlist[4];
    const float* MBp;
    if (dir == 0) { Mlist[0]=M1; Mlist[1]=M2; Mlist[2]=M3; Mlist[3]=M4; MBp=MB; }
    else          { Mlist[0]=N1; Mlist[1]=N2; Mlist[2]=N3; Mlist[3]=N4; MBp=NB; }

    int tid = threadIdx.x;
    int tj  = tid >> 5;     // warp -> j group
    int tt  = tid & 31;
    int j0  = tj * 8;
    int tt2 = tt * 2;

    u64 prod[8][4];
    u64 acc[8][4];

    for (int m = 0; m < 4; m++) {
        __syncthreads();
        // fill sMd (dup) and sV2 (pairs)
        const float* Mg = Mlist[m] + (size_t)l * 4096;
        for (int idx = tid; idx < 4096; idx += 256) {
            int j = idx >> 6, v = idx & 63;
            sMd[v*66 + j] = dup_f(Mg[idx]);
        }
        const u64* Vg = (const u64*)(g_vec + m*16384);
        for (int idx = tid; idx < 8192; idx += 256) sV2[idx] = Vg[idx];
        __syncthreads();

        #pragma unroll
        for (int jj = 0; jj < 8; jj++)
            #pragma unroll
            for (int k = 0; k < 4; k++) acc[jj][k] = 0ull;

        #pragma unroll 4
        for (int v = 0; v < 64; v++) {
            const u64* arow = sMd + v*66 + j0;
            ulonglong2 a01 = *(const ulonglong2*)(arow + 0);
            ulonglong2 a23 = *(const ulonglong2*)(arow + 2);
            ulonglong2 a45 = *(const ulonglong2*)(arow + 4);
            ulonglong2 a67 = *(const ulonglong2*)(arow + 6);
            ulonglong2 bl  = *(const ulonglong2*)(sV2 + v*128 + tt2);
            ulonglong2 bh  = *(const ulonglong2*)(sV2 + v*128 + tt2 + 64);
            u64 a8[8] = {a01.x,a01.y,a23.x,a23.y,a45.x,a45.y,a67.x,a67.y};
            u64 b4[4] = {bl.x, bl.y, bh.x, bh.y};
            #pragma unroll
            for (int jj = 0; jj < 8; jj++)
                #pragma unroll
                for (int k = 0; k < 4; k++)
                    acc[jj][k] = fma2(a8[jj], b4[k], acc[jj][k]);
        }

        if (m == 0) {
            #pragma unroll
            for (int jj = 0; jj < 8; jj++)
                #pragma unroll
                for (int k = 0; k < 4; k++) prod[jj][k] = acc[jj][k];
        } else {
            #pragma unroll
            for (int jj = 0; jj < 8; jj++)
                #pragma unroll
                for (int k = 0; k < 4; k++) prod[jj][k] = mul2(prod[jj][k], acc[jj][k]);
        }
    }

    // B-matrix term
    {
        const u64* vB0 = (const u64*)g_vB;
        const u64* vB1 = (const u64*)(g_vB + 256);
        u64 vb0[4], vb1[4];
        int pidx[4] = {tt2, tt2+1, tt2+64, tt2+65};
        #pragma unroll
        for (int k = 0; k < 4; k++) { vb0[k] = vB0[pidx[k]]; vb1[k] = vB1[pidx[k]]; }
        #pragma unroll
        for (int jj = 0; jj < 8; jj++) {
            int r = l*64 + j0 + jj;
            u64 mbp = ((const u64*)MBp)[r];
            u64 mb0 = dup_f(lo_f(mbp)), mb1 = dup_f(hi_f(mbp));
            #pragma unroll
            for (int k = 0; k < 4; k++) {
                u64 t = fma2(mb1, vb1[k], mul2(mb0, vb0[k]));
                prod[jj][k] = mul2(prod[jj][k], t);
            }
        }
    }

    // reduce over j: 8 in-thread + 8 across warps
    {
        int pidx[4] = {tt2, tt2+1, tt2+64, tt2+65};
        #pragma unroll
        for (int k = 0; k < 4; k++) {
            u64 s = prod[0][k];
            #pragma unroll
            for (int jj = 1; jj < 8; jj++) s = add2(s, prod[jj][k]);
            sRed[tj*128 + pidx[k]] = s;
        }
    }
    __syncthreads();
    const float* sRedF = (const float*)sRed;
    float s = 0.0f;
    #pragma unroll
    for (int w = 0; w < 8; w++) s += sRedF[w*256 + tid];
    g_outs[(dir*1024 + l)*256 + tid] = s;
}

// ---------------- kernel C1: combine dirs with C1/C2, boundary scaling ----------------
__global__ void k_comb()
{
    int idx = blockIdx.x * 256 + threadIdx.x;  // 128*1024
    int h = idx >> 10;
    int l = idx & 1023;
    const float* o0 = g_outs + l*256;
    const float* o1 = g_outs + 262144 + l*256;
    int t = h*2;
    float v = o0[t]*g_c1[t] + o0[t+1]*g_c1[t+1] + o1[t]*g_c2[t] + o1[t+1]*g_c2[t+1];
    int li = l >> 5, lj = l & 31;
    float f = 1.0f;
    if (li == 0) f *= 2.0f;
    if (lj == 0) f *= 2.0f;
    if (li == 0 && lj == 0) f *= 0.25f;
    g_kk[h*1024 + l] = v * f;
}

// ---------------- kernel C2: fold flips -> 63x63 correlation kernel, dup-packed ----------------
__global__ void k_keff()
{
    int dpi = threadIdx.x;   // 0..63 (63 = zero pad)
    int dqi = blockIdx.x;    // 0..62
    int c   = blockIdx.y;    // 0..31
    float v = 0.0f;
    if (dpi < 63) {
        int dp = dpi - 31, dq = dqi - 31;
        if (dp <= 0 && dq <= 0) v += g_kk[(c      )*1024 + (-dp)*32 + (-dq)];
        if (dp >= 0 && dq <= 0) v += g_kk[(c + 32 )*1024 + ( dp)*32 + (-dq)];
        if (dp <= 0 && dq >= 0) v += g_kk[(c + 64 )*1024 + (-dp)*32 + ( dq)];
        if (dp >= 0 && dq >= 0) v += g_kk[(c + 96 )*1024 + ( dp)*32 + ( dq)];
    }
    g_K2[(c*63 + dqi)*64 + dpi] = dup_f(v);
}

// ---------------- kernel X: transpose+pack x (b,i,j,c) -> (c,bp,i,j) b-pairs ----------------
__global__ void k_xt(const float* __restrict__ x)
{
    int idx = blockIdx.x * 256 + threadIdx.x;   // 524288
    int j  = idx & 63;
    int i  = (idx >> 6) & 63;
    int bp = (idx >> 12) & 3;
    int c  = idx >> 14;
    float v0 = x[(((2*bp    )*64 + i)*64 + j)*32 + c];
    float v1 = x[(((2*bp + 1)*64 + i)*64 + j)*32 + c];
    g_xt2[idx] = pack2(v0, v1);
}

// ---------------- kernel D: direct 63x63 correlation, b-pair packed f32x2 ----------------
// block: (c, bp, iq) -> 16 output rows x 64 cols x 2 batches. 256 threads = 4 row-groups x 64 j.
// smem (dynamic): sX u64[88][128] = 90112B ; sK u64[63*64] = 32256B
__global__ __launch_bounds__(256, 1) void k_conv()
{
    extern __shared__ u64 smemC[];
    u64* sX = smemC;            // [88][128]
    u64* sK = smemC + 88*128;   // [63][64]

    int c  = blockIdx.x;
    int bp = blockIdx.y;
    int i0 = blockIdx.z * 16;

    int tid = threadIdx.x;
    const u64* xp = g_xt2 + (c*4 + bp)*4096;
    for (int idx = tid; idx < 88*128; idx += 256) {
        int r  = idx >> 7, cj = idx & 127;
        int gi = i0 - 31 + r, gj = cj - 31;
        u64 v = 0ull;
        if ((unsigned)gi < 64u && (unsigned)gj < 64u) v = xp[gi*64 + gj];
        sX[idx] = v;
    }
    const u64* Kc = g_K2 + c*4032;
    for (int idx = tid; idx < 4032; idx += 256) sK[idx] = Kc[idx];
    __syncthreads();

    int j  = tid & 63;
    int ig = tid >> 6;       // 0..3
    int ib = ig * 4;
    u64 acc[4];
    #pragma unroll
    for (int r = 0; r < 4; r++) acc[r] = 0ull;

    for (int dqi = 0; dqi < 63; dqi++) {
        int col = j + dqi;
        u64 w[8];
        #pragma unroll
        for (int k = 0; k < 8; k++) w[k] = sX[(ib + k)*128 + col];
        const u64* Krow = sK + dqi*64;
        #pragma unroll
        for (int c8 = 0; c8 < 8; c8++) {
            ulonglong2 k0 = *(const ulonglong2*)(Krow + c8*8 + 0);
            ulonglong2 k1 = *(const ulonglong2*)(Krow + c8*8 + 2);
            ulonglong2 k2 = *(const ulonglong2*)(Krow + c8*8 + 4);
            ulonglong2 k3 = *(const ulonglong2*)(Krow + c8*8 + 6);
            u64 kv[8] = {k0.x,k0.y,k1.x,k1.y,k2.x,k2.y,k3.x,k3.y};
            #pragma unroll
            for (int u = 0; u < 8; u++) {
                #pragma unroll
                for (int r = 0; r < 4; r++)
                    acc[r] = fma2(kv[u], w[(u + r) & 7], acc[r]);
                w[u] = sX[(ib + c8*8 + u + 8)*128 + col];
            }
        }
    }

    u64* yp = g_yt2 + (c*4 + bp)*4096;
    #pragma unroll
    for (int r = 0; r < 4; r++)
        yp[(i0 + ib + r)*64 + j] = acc[r];
}

// ---------------- kernel E: out = y @ W^T + b ----------------
__global__ __launch_bounds__(256, 4) void k_out(const float* __restrict__ W,
                                                const float* __restrict__ bias,
                                                float* __restrict__ out)
{
    int ip = blockIdx.x;   // i pair 0..31
    int b  = blockIdx.y;   // 0..7
    __shared__ float ys[2*32*64];   // [ii][c][j]
    __shared__ float Wt[32*32];     // Wt[c][e]

    int tid = threadIdx.x;
    int bp = b >> 1, bl = b & 1;
    for (int idx = tid; idx < 4096; idx += 256) {
        int ii = idx >> 11;
        int cc = (idx >> 6) & 31;
        int jx = idx & 63;
        u64 t = g_yt2[((cc*4 + bp)*64 + ip*2 + ii)*64 + jx];
        ys[idx] = bl ? hi_f(t) : lo_f(t);
    }
    for (int idx = tid; idx < 1024; idx += 256) {
        int e = idx & 31, cc = idx >> 5;
        Wt[cc*32 + e] = W[e*32 + cc];
    }
    __syncthreads();

    int e0 = (tid & 7) * 4;
    int j0 = (tid >> 3) * 2;
    float acc[2][2][4];
    #pragma unroll
    for (int ii = 0; ii < 2; ii++)
        #pragma unroll
        for (int jj = 0; jj < 2; jj++)
            #pragma unroll
            for (int k = 0; k < 4; k++) acc[ii][jj][k] = bias[e0 + k];

    for (int cc = 0; cc < 32; cc++) {
        float yv[2][2];
        #pragma unroll
        for (int ii = 0; ii < 2; ii++)
            #pragma unroll
            for (int jj = 0; jj < 2; jj++) yv[ii][jj] = ys[ii*2048 + cc*64 + j0 + jj];
        float wv[4];
        #pragma unroll
        for (int k = 0; k < 4; k++) wv[k] = Wt[cc*32 + e0 + k];
        #pragma unroll
        for (int ii = 0; ii < 2; ii++)
            #pragma unroll
            for (int jj = 0; jj < 2; jj++)
                #pragma unroll
                for (int k = 0; k < 4; k++)
                    acc[ii][jj][k] = fmaf(yv[ii][jj], wv[k], acc[ii][jj][k]);
    }

    #pragma unroll
    for (int ii = 0; ii < 2; ii++)
        #pragma unroll
        for (int jj = 0; jj < 2; jj++) {
            float* op = out + ((size_t)((b*64 + ip*2 + ii)*64 + j0 + jj))*32 + e0;
            #pragma unroll
            for (int k = 0; k < 4; k++) op[k] = acc[ii][jj][k];
        }
}

// ---------------- launch ----------------
extern "C" void kernel_launch(void* const* d_in, const int* in_sizes, int n_in,
                              void* d_out, int out_size)
{
    const float* x    = (const float*)d_in[0];
    const float* Mh1  = (const float*)d_in[1];
    const float* Mh2  = (const float*)d_in[2];
    const float* Mh3  = (const float*)d_in[3];
    const float* Mh4  = (const float*)d_in[4];
    const float* MhB  = (const float*)d_in[5];
    const float* Mv1  = (const float*)d_in[6];
    const float* Mv2  = (const float*)d_in[7];
    const float* Mv3  = (const float*)d_in[8];
    const float* Mv4  = (const float*)d_in[9];
    const float* MvB  = (const float*)d_in[10];
    const float* A1   = (const float*)d_in[11];
    const float* A2   = (const float*)d_in[12];
    const float* A3   = (const float*)d_in[13];
    const float* A4   = (const float*)d_in[14];
    const float* B1   = (const float*)d_in[15];
    const float* B2   = (const float*)d_in[16];
    const float* C1   = (const float*)d_in[17];
    const float* C2   = (const float*)d_in[18];
    const float* W    = (const float*)d_in[19];
    const float* bias = (const float*)d_in[20];
    float* out = (float*)d_out;

    const int smemProd = (64*66 + 64*128 + 8*128) * 8;   // 107520
    const int smemConv = (88*128 + 63*64) * 8;           // 122368
    cudaFuncSetAttribute(k_prod, cudaFuncAttributeMaxDynamicSharedMemorySize, smemProd);
    cudaFuncSetAttribute(k_conv, cudaFuncAttributeMaxDynamicSharedMemorySize, smemConv);

    k_vec <<<1, 256>>>(A1, A2, A3, A4, B1, B2, C1, C2);
    k_prod<<<dim3(1024, 2), 256, smemProd>>>(Mh1, Mh2, Mh3, Mh4, MhB, Mv1, Mv2, Mv3, Mv4, MvB);
    k_comb<<<512, 256>>>();
    k_keff<<<dim3(63, 32), 64>>>();
    k_xt  <<<2048, 256>>>(x);
    k_conv<<<dim3(32, 4, 4), 256, smemConv>>>();
    k_out <<<dim3(32, 8), 256>>>(W, bias, out);
}

// round 3
// speedup vs baseline: 2.0128x; 1.2769x over previous
#include <cuda_runtime.h>
#include <math.h>

#define SCALEF 0.70710678118654752440f
typedef unsigned long long u64;

// ---------------- f32x2 helpers ----------------
__device__ __forceinline__ u64 dup_f(float x){ u64 r; asm("mov.b64 %0,{%1,%1};" : "=l"(r) : "f"(x)); return r; }
__device__ __forceinline__ u64 pack2(float lo, float hi){ u64 r; asm("mov.b64 %0,{%1,%2};" : "=l"(r) : "f"(lo), "f"(hi)); return r; }
__device__ __forceinline__ u64 fma2(u64 a, u64 b, u64 c){ u64 d; asm("fma.rn.f32x2 %0,%1,%2,%3;" : "=l"(d) : "l"(a),"l"(b),"l"(c)); return d; }
__device__ __forceinline__ u64 mul2(u64 a, u64 b){ u64 d; asm("mul.rn.f32x2 %0,%1,%2;" : "=l"(d) : "l"(a),"l"(b)); return d; }
__device__ __forceinline__ u64 add2(u64 a, u64 b){ u64 d; asm("add.rn.f32x2 %0,%1,%2;" : "=l"(d) : "l"(a),"l"(b)); return d; }
__device__ __forceinline__ float lo_f(u64 x){ float a,b; asm("mov.b64 {%0,%1},%2;" : "=f"(a),"=f"(b) : "l"(x)); return a; }
__device__ __forceinline__ float hi_f(u64 x){ float a,b; asm("mov.b64 {%0,%1},%2;" : "=f"(a),"=f"(b) : "l"(x)); return b; }

// ---------------- scratch ----------------
__device__ float g_vec[4*64*256];      // a^v tables  [m][v][hn]
__device__ float g_vB[2*256];          // sigmoid(B1), sigmoid(B2)
__device__ float g_c1[256];
__device__ float g_c2[256];
__device__ float g_outs[2*1024*256];   // [dir][l][hn]
__device__ float g_kk[128*1024];       // conv kernel [h][l], boundary-scaled
__device__ float g_Kf[32*63*64];       // combined corr kernel [c][dqi][dpi pad64] (plain float)
__device__ u64   g_xt2[32*4*64*64];    // x, b-pair packed: [c][bp][i][j]
__device__ u64   g_yt2[32*4*64*64];    // conv output, same packing

// ---------------- kernel A: build vec tables (parallel) ----------------
__global__ void k_vec(const float* __restrict__ A1, const float* __restrict__ A2,
                      const float* __restrict__ A3, const float* __restrict__ A4,
                      const float* __restrict__ B1, const float* __restrict__ B2,
                      const float* __restrict__ C1, const float* __restrict__ C2)
{
    int idx = blockIdx.x * 256 + threadIdx.x;   // 65536 = 4m * 64v * 256hn
    int t = idx & 255;
    int v = (idx >> 8) & 63;
    int m = idx >> 14;
    const float* As[4] = {A1, A2, A3, A4};
    float a = 1.0f / (1.0f + expf(-As[m][t]));
    float p = (v == 0) ? 1.0f : exp2f((float)v * log2f(a));
    g_vec[idx] = p;
    if (idx < 256) {
        g_vB[t]       = 1.0f / (1.0f + expf(-B1[t]));
        g_vB[256 + t] = 1.0f / (1.0f + expf(-B2[t]));
        g_c1[t] = C1[t] * SCALEF;
        g_c2[t] = C2[t] * SCALEF;
    }
}

// ---------------- kernel B: GEMM-product + segment reduction ----------------
// block = (l, dir, hh). outs[dir][l][hh*128 + :128] over sum_j of prod_m
// tile: 8j x 2 u64 hn per thread -> no register spill.
// smem: sV2 u64[64][64] (32KB) + sRed u64[8][64] (4KB) + sM float[64][68] (17.4KB)
__global__ __launch_bounds__(256, 2) void k_prod(
    const float* __restrict__ M1, const float* __restrict__ M2,
    const float* __restrict__ M3, const float* __restrict__ M4,
    const float* __restrict__ MB,
    const float* __restrict__ N1, const float* __restrict__ N2,
    const float* __restrict__ N3, const float* __restrict__ N4,
    const float* __restrict__ NB)
{
    extern __shared__ u64 smemP[];
    u64*   sV2  = smemP;                  // 64*64
    u64*   sRed = smemP + 64*64;          // 8*64
    float* sM   = (float*)(smemP + 64*64 + 8*64);  // 64*68

    int l   = blockIdx.x;
    int dir = blockIdx.y;
    int hh  = blockIdx.z;   // hn half: 0 or 1
    const float* Mlist[4];
    const float* MBp;
    if (dir == 0) { Mlist[0]=M1; Mlist[1]=M2; Mlist[2]=M3; Mlist[3]=M4; MBp=MB; }
    else          { Mlist[0]=N1; Mlist[1]=N2; Mlist[2]=N3; Mlist[3]=N4; MBp=NB; }

    int tid = threadIdx.x;
    int tj  = tid >> 5;     // warp -> j group (uniform within warp)
    int tt  = tid & 31;
    int j0  = tj * 8;
    int p0  = tt * 2;       // u64 index within 64-u64 half

    u64 prod[8][2];
    u64 acc[8][2];

    for (int m = 0; m < 4; m++) {
        __syncthreads();
        const float* Mg = Mlist[m] + (size_t)l * 4096;
        for (int idx = tid; idx < 4096; idx += 256) {
            int j = idx >> 6, v = idx & 63;
            sM[v*68 + j] = Mg[idx];
        }
        const u64* Vg = (const u64*)(g_vec + m*16384) + hh*64;
        for (int idx = tid; idx < 4096; idx += 256) {
            int v = idx >> 6, i = idx & 63;
            sV2[v*64 + i] = Vg[v*128 + i];
        }
        __syncthreads();

        #pragma unroll
        for (int jj = 0; jj < 8; jj++)
            #pragma unroll
            for (int k = 0; k < 2; k++) acc[jj][k] = 0ull;

        #pragma unroll 4
        for (int v = 0; v < 64; v++) {
            const float4* arow = (const float4*)(sM + v*68 + j0);
            float4 a03 = arow[0];
            float4 a47 = arow[1];
            ulonglong2 bp = *(const ulonglong2*)(sV2 + v*64 + p0);
            u64 a8[8] = {dup_f(a03.x), dup_f(a03.y), dup_f(a03.z), dup_f(a03.w),
                         dup_f(a47.x), dup_f(a47.y), dup_f(a47.z), dup_f(a47.w)};
            u64 b2[2] = {bp.x, bp.y};
            #pragma unroll
            for (int jj = 0; jj < 8; jj++)
                #pragma unroll
                for (int k = 0; k < 2; k++)
                    acc[jj][k] = fma2(a8[jj], b2[k], acc[jj][k]);
        }

        if (m == 0) {
            #pragma unroll
            for (int jj = 0; jj < 8; jj++)
                #pragma unroll
                for (int k = 0; k < 2; k++) prod[jj][k] = acc[jj][k];
        } else {
            #pragma unroll
            for (int jj = 0; jj < 8; jj++)
                #pragma unroll
                for (int k = 0; k < 2; k++) prod[jj][k] = mul2(prod[jj][k], acc[jj][k]);
        }
    }

    // B-matrix term: *= MB[r,0]*sigB1[hn] + MB[r,1]*sigB2[hn]
    {
        const u64* vBu = (const u64*)g_vB;
        u64 vb0[2], vb1[2];
        #pragma unroll
        for (int k = 0; k < 2; k++) {
            vb0[k] = vBu[hh*64 + p0 + k];
            vb1[k] = vBu[128 + hh*64 + p0 + k];
        }
        #pragma unroll
        for (int jj = 0; jj < 8; jj++) {
            int r = l*64 + j0 + jj;
            u64 mbp = ((const u64*)MBp)[r];
            u64 mb0 = dup_f(lo_f(mbp)), mb1 = dup_f(hi_f(mbp));
            #pragma unroll
            for (int k = 0; k < 2; k++) {
                u64 t = fma2(mb1, vb1[k], mul2(mb0, vb0[k]));
                prod[jj][k] = mul2(prod[jj][k], t);
            }
        }
    }

    // reduce over j: 8 in-thread + 8 across warps
    #pragma unroll
    for (int k = 0; k < 2; k++) {
        u64 s = prod[0][k];
        #pragma unroll
        for (int jj = 1; jj < 8; jj++) s = add2(s, prod[jj][k]);
        sRed[tj*64 + p0 + k] = s;
    }
    __syncthreads();
    if (tid < 128) {
        const float* sRedF = (const float*)sRed;
        float s = 0.0f;
        #pragma unroll
        for (int w = 0; w < 8; w++) s += sRedF[w*128 + tid];
        g_outs[(dir*1024 + l)*256 + hh*128 + tid] = s;
    }
}

// ---------------- kernel C1: combine dirs with C1/C2, boundary scaling ----------------
__global__ void k_comb()
{
    int idx = blockIdx.x * 256 + threadIdx.x;  // 128*1024
    int h = idx >> 10;
    int l = idx & 1023;
    const float* o0 = g_outs + l*256;
    const float* o1 = g_outs + 262144 + l*256;
    int t = h*2;
    float v = o0[t]*g_c1[t] + o0[t+1]*g_c1[t+1] + o1[t]*g_c2[t] + o1[t+1]*g_c2[t+1];
    int li = l >> 5, lj = l & 31;
    float f = 1.0f;
    if (li == 0) f *= 2.0f;
    if (lj == 0) f *= 2.0f;
    if (li == 0 && lj == 0) f *= 0.25f;
    g_kk[h*1024 + l] = v * f;
}

// ---------------- kernel C2: fold flips -> 63x63 correlation kernel (plain float) ----------------
__global__ void k_keff()
{
    int dpi = threadIdx.x;   // 0..63 (63 = zero pad)
    int dqi = blockIdx.x;    // 0..62
    int c   = blockIdx.y;    // 0..31
    float v = 0.0f;
    if (dpi < 63) {
        int dp = dpi - 31, dq = dqi - 31;
        if (dp <= 0 && dq <= 0) v += g_kk[(c      )*1024 + (-dp)*32 + (-dq)];
        if (dp >= 0 && dq <= 0) v += g_kk[(c + 32 )*1024 + ( dp)*32 + (-dq)];
        if (dp <= 0 && dq >= 0) v += g_kk[(c + 64 )*1024 + (-dp)*32 + ( dq)];
        if (dp >= 0 && dq >= 0) v += g_kk[(c + 96 )*1024 + ( dp)*32 + ( dq)];
    }
    g_Kf[(c*63 + dqi)*64 + dpi] = v;
}

// ---------------- kernel X: transpose+pack x (b,i,j,c) -> (c,bp,i,j) b-pairs ----------------
__global__ void k_xt(const float* __restrict__ x)
{
    int idx = blockIdx.x * 256 + threadIdx.x;   // 524288
    int j  = idx & 63;
    int i  = (idx >> 6) & 63;
    int bp = (idx >> 12) & 3;
    int c  = idx >> 14;
    float v0 = x[(((2*bp    )*64 + i)*64 + j)*32 + c];
    float v1 = x[(((2*bp + 1)*64 + i)*64 + j)*32 + c];
    g_xt2[idx] = pack2(v0, v1);
}

// ---------------- kernel D: direct 63x63 correlation, b-pair packed f32x2 ----------------
// block: (c, bp, iq) -> 16 output rows x 64 cols x 2 batches.
// smem: sX u64[84][128] (86016B) + sK float[63][64] (16128B) = 102144B -> 2 blocks/SM
__global__ __launch_bounds__(256, 2) void k_conv()
{
    extern __shared__ u64 smemC[];
    u64*   sX = smemC;                 // [84][128]
    float* sK = (float*)(smemC + 84*128);  // [63][64]

    int c  = blockIdx.x;
    int bp = blockIdx.y;
    int i0 = blockIdx.z * 16;

    int tid = threadIdx.x;
    const u64* xp = g_xt2 + (c*4 + bp)*4096;
    for (int idx = tid; idx < 84*128; idx += 256) {
        int r  = idx >> 7, cj = idx & 127;
        int gi = i0 - 31 + r, gj = cj - 31;
        u64 v = 0ull;
        if ((unsigned)gi < 64u && (unsigned)gj < 64u) v = xp[gi*64 + gj];
        sX[idx] = v;
    }
    const float* Kc = g_Kf + c*4032;
    for (int idx = tid; idx < 4032; idx += 256) sK[idx] = Kc[idx];
    __syncthreads();

    int j  = tid & 63;
    int ig = tid >> 6;       // 0..3
    int ib = ig * 4;
    u64 acc[4];
    #pragma unroll
    for (int r = 0; r < 4; r++) acc[r] = 0ull;

    for (int dqi = 0; dqi < 63; dqi++) {
        int col = j + dqi;
        u64 w[8];
        #pragma unroll
        for (int k = 0; k < 8; k++) w[k] = sX[(ib + k)*128 + col];
        const float* Krow = sK + dqi*64;
        #pragma unroll
        for (int c8 = 0; c8 < 8; c8++) {
            const float4* kp = (const float4*)(Krow + c8*8);
            float4 k03 = kp[0];
            float4 k47 = kp[1];
            u64 kv[8] = {dup_f(k03.x), dup_f(k03.y), dup_f(k03.z), dup_f(k03.w),
                         dup_f(k47.x), dup_f(k47.y), dup_f(k47.z), dup_f(k47.w)};
            #pragma unroll
            for (int u = 0; u < 8; u++) {
                #pragma unroll
                for (int r = 0; r < 4; r++)
                    acc[r] = fma2(kv[u], w[(u + r) & 7], acc[r]);
                w[u] = sX[(ib + c8*8 + u + 8)*128 + col];
            }
        }
    }

    u64* yp = g_yt2 + (c*4 + bp)*4096;
    #pragma unroll
    for (int r = 0; r < 4; r++)
        yp[(i0 + ib + r)*64 + j] = acc[r];
}

// ---------------- kernel E: out = y @ W^T + b ----------------
__global__ __launch_bounds__(256, 4) void k_out(const float* __restrict__ W,
                                                const float* __restrict__ bias,
                                                float* __restrict__ out)
{
    int ip = blockIdx.x;   // i pair 0..31
    int b  = blockIdx.y;   // 0..7
    __shared__ float ys[2*32*64];   // [ii][c][j]
    __shared__ float Wt[32*32];     // Wt[c][e]

    int tid = threadIdx.x;
    int bp = b >> 1, bl = b & 1;
    for (int idx = tid; idx < 4096; idx += 256) {
        int ii = idx >> 11;
        int cc = (idx >> 6) & 31;
        int jx = idx & 63;
        u64 t = g_yt2[((cc*4 + bp)*64 + ip*2 + ii)*64 + jx];
        ys[idx] = bl ? hi_f(t) : lo_f(t);
    }
    for (int idx = tid; idx < 1024; idx += 256) {
        int e = idx & 31, cc = idx >> 5;
        Wt[cc*32 + e] = W[e*32 + cc];
    }
    __syncthreads();

    int e0 = (tid & 7) * 4;
    int j0 = (tid >> 3) * 2;
    float acc[2][2][4];
    #pragma unroll
    for (int ii = 0; ii < 2; ii++)
        #pragma unroll
        for (int jj = 0; jj < 2; jj++)
            #pragma unroll
            for (int k = 0; k < 4; k++) acc[ii][jj][k] = bias[e0 + k];

    for (int cc = 0; cc < 32; cc++) {
        float yv[2][2];
        #pragma unroll
        for (int ii = 0; ii < 2; ii++)
            #pragma unroll
            for (int jj = 0; jj < 2; jj++) yv[ii][jj] = ys[ii*2048 + cc*64 + j0 + jj];
        float wv[4];
        #pragma unroll
        for (int k = 0; k < 4; k++) wv[k] = Wt[cc*32 + e0 + k];
        #pragma unroll
        for (int ii = 0; ii < 2; ii++)
            #pragma unroll
            for (int jj = 0; jj < 2; jj++)
                #pragma unroll
                for (int k = 0; k < 4; k++)
                    acc[ii][jj][k] = fmaf(yv[ii][jj], wv[k], acc[ii][jj][k]);
    }

    #pragma unroll
    for (int ii = 0; ii < 2; ii++)
        #pragma unroll
        for (int jj = 0; jj < 2; jj++) {
            float* op = out + ((size_t)((b*64 + ip*2 + ii)*64 + j0 + jj))*32 + e0;
            #pragma unroll
            for (int k = 0; k < 4; k++) op[k] = acc[ii][jj][k];
        }
}

// ---------------- launch ----------------
extern "C" void kernel_launch(void* const* d_in, const int* in_sizes, int n_in,
                              void* d_out, int out_size)
{
    const float* x    = (const float*)d_in[0];
    const float* Mh1  = (const float*)d_in[1];
    const float* Mh2  = (const float*)d_in[2];
    const float* Mh3  = (const float*)d_in[3];
    const float* Mh4  = (const float*)d_in[4];
    const float* MhB  = (const float*)d_in[5];
    const float* Mv1  = (const float*)d_in[6];
    const float* Mv2  = (const float*)d_in[7];
    const float* Mv3  = (const float*)d_in[8];
    const float* Mv4  = (const float*)d_in[9];
    const float* MvB  = (const float*)d_in[10];
    const float* A1   = (const float*)d_in[11];
    const float* A2   = (const float*)d_in[12];
    const float* A3   = (const float*)d_in[13];
    const float* A4   = (const float*)d_in[14];
    const float* B1   = (const float*)d_in[15];
    const float* B2   = (const float*)d_in[16];
    const float* C1   = (const float*)d_in[17];
    const float* C2   = (const float*)d_in[18];
    const float* W    = (const float*)d_in[19];
    const float* bias = (const float*)d_in[20];
    float* out = (float*)d_out;

    const int smemProd = (64*64 + 8*64) * 8 + 64*68*4;      // 32768+4096+17408 = 54272
    const int smemConv = 84*128*8 + 63*64*4;                // 86016+16128 = 102144
    cudaFuncSetAttribute(k_prod, cudaFuncAttributeMaxDynamicSharedMemorySize, smemProd);
    cudaFuncSetAttribute(k_conv, cudaFuncAttributeMaxDynamicSharedMemorySize, smemConv);

    k_vec <<<256, 256>>>(A1, A2, A3, A4, B1, B2, C1, C2);
    k_prod<<<dim3(1024, 2, 2), 256, smemProd>>>(Mh1, Mh2, Mh3, Mh4, MhB, Mv1, Mv2, Mv3, Mv4, MvB);
    k_comb<<<512, 256>>>();
    k_keff<<<dim3(63, 32), 64>>>();
    k_xt  <<<2048, 256>>>(x);
    k_conv<<<dim3(32, 4, 4), 256, smemConv>>>();
    k_out <<<dim3(32, 8), 256>>>(W, bias, out);
}